// round 3
// baseline (speedup 1.0000x reference)
#include <cuda_runtime.h>
#include <cuda_fp16.h>
#include <cstdint>

// ---------------- problem constants ----------------
#define BB    64
#define HH    64
#define WWID  64
#define CINC  128
#define COUTC 256
#define HOUT  62
#define WOUT  62
#define MM    3844   // 62*62
#define KKTOT 1152   // 9*128
#define NNTOT 256

// ---------------- GEMM tiling ----------------
#define BM     128
#define BN     256          // full N per CTA
#define BK     32
#define NIT    (KKTOT / BK) // 36
#define STAGES 3
#define NTHREADS 256

// smem layout (halves): As[s][128][40], Bs[s][32][264]
#define A_ROW_H   40
#define B_ROW_H   264
#define A_ST_H    (BM * A_ROW_H)          // 5120 halves = 10240 B
#define B_ST_H    (BK * B_ROW_H)          // 8448 halves = 16896 B
#define SMEM_MB   0                       // 256 f32 membias = 1024 B
#define SMEM_A    1024
#define SMEM_B    (SMEM_A + STAGES * A_ST_H * 2)      // 1024 + 30720 = 31744
#define SMEM_TOTAL (SMEM_B + STAGES * B_ST_H * 2)     // 31744 + 50688 = 82432

// ---------------- scratch ----------------
__device__ __half g_Xh[(size_t)BB * HH * WWID * CINC];   // X fp16, NHWC
__device__ __half g_Wh[(size_t)BB * KKTOT * COUTC];      // memW fp16, [b][k][n]

// ---------------- prep 1: X f32 -> fp16 ----------------
__global__ void convert_x_kernel(const float* __restrict__ X) {
    size_t i = ((size_t)blockIdx.x * blockDim.x + threadIdx.x) * 4;
    float4 v = *reinterpret_cast<const float4*>(X + i);
    __half2 h0 = __floats2half2_rn(v.x, v.y);
    __half2 h1 = __floats2half2_rn(v.z, v.w);
    uint2 o;
    o.x = *reinterpret_cast<uint32_t*>(&h0);
    o.y = *reinterpret_cast<uint32_t*>(&h1);
    *reinterpret_cast<uint2*>(g_Xh + i) = o;
}

// ---------------- prep 2: memW = W*Werr -> fp16, layout [b][k][n] ----------------
__global__ void convert_w_kernel(const float* __restrict__ W,
                                 const float* __restrict__ Werr) {
    size_t i = ((size_t)blockIdx.x * blockDim.x + threadIdx.x) * 4;
    size_t wi = i % ((size_t)KKTOT * COUTC);
    float4 w = *reinterpret_cast<const float4*>(W + wi);
    float4 e = *reinterpret_cast<const float4*>(Werr + i);
    __half2 h0 = __floats2half2_rn(w.x * e.x, w.y * e.y);
    __half2 h1 = __floats2half2_rn(w.z * e.z, w.w * e.w);
    uint2 o;
    o.x = *reinterpret_cast<uint32_t*>(&h0);
    o.y = *reinterpret_cast<uint32_t*>(&h1);
    *reinterpret_cast<uint2*>(g_Wh + i) = o;
}

// ---------------- PTX helpers ----------------
__device__ __forceinline__ void cp16(uint32_t dst, const void* src) {
    asm volatile("cp.async.cg.shared.global [%0], [%1], 16;\n" :: "r"(dst), "l"(src));
}
__device__ __forceinline__ void cp_commit() {
    asm volatile("cp.async.commit_group;\n" ::: "memory");
}
template <int N>
__device__ __forceinline__ void cp_wait() {
    asm volatile("cp.async.wait_group %0;\n" :: "n"(N) : "memory");
}
__device__ __forceinline__ void ldmatrix_x4(uint32_t* r, uint32_t addr) {
    asm volatile("ldmatrix.sync.aligned.m8n8.x4.shared.b16 {%0,%1,%2,%3}, [%4];\n"
                 : "=r"(r[0]), "=r"(r[1]), "=r"(r[2]), "=r"(r[3]) : "r"(addr));
}
__device__ __forceinline__ void ldmatrix_x2_trans(uint32_t* r, uint32_t addr) {
    asm volatile("ldmatrix.sync.aligned.m8n8.x2.trans.shared.b16 {%0,%1}, [%2];\n"
                 : "=r"(r[0]), "=r"(r[1]) : "r"(addr));
}
__device__ __forceinline__ void mma16816(float* c, const uint32_t* a, const uint32_t* b) {
    asm volatile(
        "mma.sync.aligned.m16n8k16.row.col.f32.f16.f16.f32 "
        "{%0,%1,%2,%3}, {%4,%5,%6,%7}, {%8,%9}, {%0,%1,%2,%3};\n"
        : "+f"(c[0]), "+f"(c[1]), "+f"(c[2]), "+f"(c[3])
        : "r"(a[0]), "r"(a[1]), "r"(a[2]), "r"(a[3]), "r"(b[0]), "r"(b[1]));
}

// ---------------- main kernel ----------------
// grid = (31, 64), 256 threads (8 warps in 2x4; warp tile 64x64)
__global__ __launch_bounds__(NTHREADS, 1)
void conv_gemm_kernel(const float* __restrict__ bias,
                      const float* __restrict__ Berr,
                      float* __restrict__ out) {
    extern __shared__ __align__(16) char smem[];
    const uint32_t sbase = (uint32_t)__cvta_generic_to_shared(smem);
    float* smb = reinterpret_cast<float*>(smem + SMEM_MB);

    const int tid  = threadIdx.x;
    const int warp = tid >> 5;
    const int lane = tid & 31;
    const int wm = warp >> 2;   // 0..1
    const int wn = warp & 3;    // 0..3
    const int m0 = blockIdx.x * BM;
    const int b  = blockIdx.y;

    // membias -> smem
    smb[tid] = bias[tid] * Berr[b * COUTC + tid];

    float acc[4][8][4];
    #pragma unroll
    for (int mf = 0; mf < 4; mf++)
        #pragma unroll
        for (int nf = 0; nf < 8; nf++)
            #pragma unroll
            for (int r = 0; r < 4; r++) acc[mf][nf][r] = 0.f;

    // A-load descriptors: 512 16B chunks/stage -> 2 per thread
    int arow[2], aseg[2];
    size_t abase[2];
    #pragma unroll
    for (int j = 0; j < 2; j++) {
        int c = tid + j * 256;
        arow[j] = c >> 2;
        aseg[j] = c & 3;
        int m = m0 + arow[j];
        if (m >= MM) m = 0;
        int ho = m / WOUT;
        int wo = m - ho * WOUT;
        abase[j] = (((size_t)b * HH + ho) * WWID + wo) * CINC;
    }
    const size_t wbase = (size_t)b * KKTOT * COUTC;

    auto issue_stage = [&](int it, int slot) {
        const int k0 = it * BK;
        const int tap = k0 >> 7;
        const int c0  = k0 & 127;
        const int kh  = tap / 3;
        const int kw  = tap - kh * 3;
        const size_t tapoff = ((size_t)kh * WWID + kw) * CINC + c0;
        const uint32_t a0 = sbase + SMEM_A + slot * A_ST_H * 2;
        const uint32_t b0 = sbase + SMEM_B + slot * B_ST_H * 2;
        #pragma unroll
        for (int j = 0; j < 2; j++) {
            const __half* src = g_Xh + abase[j] + tapoff + aseg[j] * 8;
            cp16(a0 + (arow[j] * A_ROW_H + aseg[j] * 8) * 2, src);
        }
        #pragma unroll
        for (int j = 0; j < 4; j++) {     // B: 32 rows x 32 chunks = 1024
            int c = tid + j * 256;
            int row = c >> 5;
            int seg = c & 31;
            const __half* src = g_Wh + wbase + (size_t)(k0 + row) * COUTC + seg * 8;
            cp16(b0 + (row * B_ROW_H + seg * 8) * 2, src);
        }
    };

    // prologue
    issue_stage(0, 0); cp_commit();
    issue_stage(1, 1); cp_commit();

    for (int it = 0; it < NIT; it++) {
        const int s = it % STAGES;
        if (it == NIT - 1) cp_wait<0>(); else cp_wait<1>();
        __syncthreads();
        if (it + 2 < NIT) {
            issue_stage(it + 2, (it + 2) % STAGES);
            cp_commit();
        }

        const uint32_t aS = sbase + SMEM_A + s * A_ST_H * 2;
        const uint32_t bS = sbase + SMEM_B + s * B_ST_H * 2;
        #pragma unroll
        for (int ks = 0; ks < 2; ks++) {
            uint32_t afr[4][4];
            const int arL  = wm * 64 + (lane & 15);
            const int acol = ks * 16 + ((lane >> 4) << 3);
            #pragma unroll
            for (int mf = 0; mf < 4; mf++)
                ldmatrix_x4(afr[mf], aS + ((arL + mf * 16) * A_ROW_H + acol) * 2);

            uint32_t bfr[8][2];
            const int brL = ks * 16 + (lane & 15);
            #pragma unroll
            for (int nf = 0; nf < 8; nf++)
                ldmatrix_x2_trans(bfr[nf], bS + (brL * B_ROW_H + wn * 64 + nf * 8) * 2);

            #pragma unroll
            for (int mf = 0; mf < 4; mf++)
                #pragma unroll
                for (int nf = 0; nf < 8; nf++)
                    mma16816(acc[mf][nf], afr[mf], bfr[nf]);
        }
        // next-iteration top __syncthreads covers WAR on stage s
    }
    __syncthreads();   // membias smem visibility (cheap; also orders epilogue)

    // epilogue: fused noisy bias + store
    const int gid = lane >> 2;
    const int tg  = lane & 3;
    #pragma unroll
    for (int nf = 0; nf < 8; nf++) {
        const int cc = wn * 64 + nf * 8 + tg * 2;
        const float mb0 = smb[cc];
        const float mb1 = smb[cc + 1];
        #pragma unroll
        for (int mf = 0; mf < 4; mf++) {
            const int r0 = m0 + wm * 64 + mf * 16 + gid;
            if (r0 < MM) {
                float2 v = make_float2(acc[mf][nf][0] + mb0, acc[mf][nf][1] + mb1);
                *reinterpret_cast<float2*>(&out[((size_t)b * MM + r0) * NNTOT + cc]) = v;
            }
            const int r1 = r0 + 8;
            if (r1 < MM) {
                float2 v = make_float2(acc[mf][nf][2] + mb0, acc[mf][nf][3] + mb1);
                *reinterpret_cast<float2*>(&out[((size_t)b * MM + r1) * NNTOT + cc]) = v;
            }
        }
    }
}

// ---------------- launch ----------------
extern "C" void kernel_launch(void* const* d_in, const int* in_sizes, int n_in,
                              void* d_out, int out_size) {
    (void)in_sizes; (void)n_in; (void)out_size;
    const float* X    = (const float*)d_in[0];
    const float* W    = (const float*)d_in[1];
    const float* bias = (const float*)d_in[2];
    const float* Werr = (const float*)d_in[3];
    const float* Berr = (const float*)d_in[4];
    float* out = (float*)d_out;

    convert_x_kernel<<<32768, 256>>>(X);
    convert_w_kernel<<<18432, 256>>>(W, Werr);

    static bool attr_set = false;
    if (!attr_set) {
        cudaFuncSetAttribute(conv_gemm_kernel,
                             cudaFuncAttributeMaxDynamicSharedMemorySize, SMEM_TOTAL);
        attr_set = true;
    }
    dim3 grid((MM + BM - 1) / BM, BB);   // (31, 64)
    conv_gemm_kernel<<<grid, NTHREADS, SMEM_TOTAL>>>(bias, Berr, out);
}

// round 4
// speedup vs baseline: 1.1752x; 1.1752x over previous
#include <cuda_runtime.h>
#include <cuda_fp16.h>
#include <cstdint>

// ---------------- problem constants ----------------
#define BB    64
#define HH    64
#define WWID  64
#define CINC  128
#define COUTC 256
#define HOUT  62
#define WOUT  62
#define MM    3844
#define KKTOT 1152
#define NNTOT 256

// ---------------- GEMM tiling (R1 proven shape) ----------------
#define BM     128
#define BN     128
#define BK     32
#define NIT    (KKTOT / BK)   // 36
#define STAGES 3
#define NTHREADS 256

// smem (halves): As[s][128][40], Bs[s][32][136]
#define A_ROW_H 40
#define B_ROW_H 136
#define A_ST_H  (BM * A_ROW_H)   // 5120
#define B_ST_H  (BK * B_ROW_H)   // 4352
#define SMEM_A  0
#define SMEM_B  (STAGES * A_ST_H * 2)                 // 30720
#define SMEM_TOTAL (SMEM_B + STAGES * B_ST_H * 2)     // 56832

// ---------------- scratch ----------------
__device__ __half g_Xh[(size_t)BB * HH * WWID * CINC];   // X fp16 NHWC
__device__ __half g_Wh[(size_t)BB * KKTOT * COUTC];      // memW fp16 [b][k][n]

// ---------------- fused prep: X->fp16 and memW=W*Werr->fp16 ----------------
#define XBLOCKS 32768   // 33.55M elems / 4 per thread / 256
#define WBLOCKS 18432   // 18.87M / 4 / 256
__global__ void prep_kernel(const float* __restrict__ X,
                            const float* __restrict__ W,
                            const float* __restrict__ Werr) {
    if (blockIdx.x < XBLOCKS) {
        size_t i = ((size_t)blockIdx.x * blockDim.x + threadIdx.x) * 4;
        float4 v = *reinterpret_cast<const float4*>(X + i);
        __half2 h0 = __floats2half2_rn(v.x, v.y);
        __half2 h1 = __floats2half2_rn(v.z, v.w);
        uint2 o;
        o.x = *reinterpret_cast<uint32_t*>(&h0);
        o.y = *reinterpret_cast<uint32_t*>(&h1);
        *reinterpret_cast<uint2*>(g_Xh + i) = o;
    } else {
        size_t i = ((size_t)(blockIdx.x - XBLOCKS) * blockDim.x + threadIdx.x) * 4;
        size_t wi = i % ((size_t)KKTOT * COUTC);
        float4 w = *reinterpret_cast<const float4*>(W + wi);
        float4 e = *reinterpret_cast<const float4*>(Werr + i);
        __half2 h0 = __floats2half2_rn(w.x * e.x, w.y * e.y);
        __half2 h1 = __floats2half2_rn(w.z * e.z, w.w * e.w);
        uint2 o;
        o.x = *reinterpret_cast<uint32_t*>(&h0);
        o.y = *reinterpret_cast<uint32_t*>(&h1);
        *reinterpret_cast<uint2*>(g_Wh + i) = o;
    }
}

// ---------------- PTX helpers ----------------
__device__ __forceinline__ void cp16(uint32_t dst, const void* src) {
    asm volatile("cp.async.cg.shared.global [%0], [%1], 16;\n" :: "r"(dst), "l"(src));
}
__device__ __forceinline__ void cp_commit() {
    asm volatile("cp.async.commit_group;\n" ::: "memory");
}
template <int N>
__device__ __forceinline__ void cp_wait() {
    asm volatile("cp.async.wait_group %0;\n" :: "n"(N) : "memory");
}
__device__ __forceinline__ void ldmatrix_x4(uint32_t* r, uint32_t addr) {
    asm volatile("ldmatrix.sync.aligned.m8n8.x4.shared.b16 {%0,%1,%2,%3}, [%4];\n"
                 : "=r"(r[0]), "=r"(r[1]), "=r"(r[2]), "=r"(r[3]) : "r"(addr));
}
__device__ __forceinline__ void ldmatrix_x2_trans(uint32_t* r, uint32_t addr) {
    asm volatile("ldmatrix.sync.aligned.m8n8.x2.trans.shared.b16 {%0,%1}, [%2];\n"
                 : "=r"(r[0]), "=r"(r[1]) : "r"(addr));
}
__device__ __forceinline__ void mma16816(float* c, const uint32_t* a, const uint32_t* b) {
    asm volatile(
        "mma.sync.aligned.m16n8k16.row.col.f32.f16.f16.f32 "
        "{%0,%1,%2,%3}, {%4,%5,%6,%7}, {%8,%9}, {%0,%1,%2,%3};\n"
        : "+f"(c[0]), "+f"(c[1]), "+f"(c[2]), "+f"(c[3])
        : "r"(a[0]), "r"(a[1]), "r"(a[2]), "r"(a[3]), "r"(b[0]), "r"(b[1]));
}

// ---------------- main GEMM ----------------
// grid (2, 31, 64), 256 threads (2x4 warps, warp tile 64x32)
__global__ __launch_bounds__(NTHREADS, 2)
void conv_gemm_kernel(const float* __restrict__ bias,
                      const float* __restrict__ Berr,
                      float* __restrict__ out) {
    extern __shared__ __align__(16) char smem[];
    const uint32_t sbase = (uint32_t)__cvta_generic_to_shared(smem);

    const int tid  = threadIdx.x;
    const int warp = tid >> 5;
    const int lane = tid & 31;
    const int wm = warp >> 2;
    const int wn = warp & 3;
    const int n0 = blockIdx.x * BN;
    const int m0 = blockIdx.y * BM;
    const int b  = blockIdx.z;

    float acc[4][4][4];
    #pragma unroll
    for (int mf = 0; mf < 4; mf++)
        #pragma unroll
        for (int nf = 0; nf < 4; nf++)
            #pragma unroll
            for (int r = 0; r < 4; r++) acc[mf][nf][r] = 0.f;

    // A: 512 chunks/stage -> 2/thread
    int arow[2], aseg[2];
    size_t abase[2];
    #pragma unroll
    for (int j = 0; j < 2; j++) {
        int c = tid + j * 256;
        arow[j] = c >> 2;
        aseg[j] = c & 3;
        int m = m0 + arow[j];
        if (m >= MM) m = 0;
        int ho = m / WOUT;
        int wo = m - ho * WOUT;
        abase[j] = (((size_t)b * HH + ho) * WWID + wo) * CINC;
    }
    const size_t wbase = (size_t)b * KKTOT * COUTC;

    auto issue_stage = [&](int it, int slot) {
        const int k0 = it * BK;
        const int tap = k0 >> 7;
        const int c0  = k0 & 127;
        const int kh  = tap / 3;
        const int kw  = tap - kh * 3;
        const size_t tapoff = ((size_t)kh * WWID + kw) * CINC + c0;
        const uint32_t a0 = sbase + SMEM_A + slot * A_ST_H * 2;
        const uint32_t b0 = sbase + SMEM_B + slot * B_ST_H * 2;
        #pragma unroll
        for (int j = 0; j < 2; j++) {
            const __half* src = g_Xh + abase[j] + tapoff + aseg[j] * 8;
            cp16(a0 + (arow[j] * A_ROW_H + aseg[j] * 8) * 2, src);
        }
        #pragma unroll
        for (int j = 0; j < 2; j++) {      // B: 32 rows x 16 chunks = 512
            int c = tid + j * 256;
            int row = c >> 4;
            int seg = c & 15;
            const __half* src = g_Wh + wbase + (size_t)(k0 + row) * COUTC + n0 + seg * 8;
            cp16(b0 + (row * B_ROW_H + seg * 8) * 2, src);
        }
    };

    issue_stage(0, 0); cp_commit();
    issue_stage(1, 1); cp_commit();

    for (int it = 0; it < NIT; it++) {
        const int s = it % STAGES;
        if (it == NIT - 1) cp_wait<0>(); else cp_wait<1>();
        __syncthreads();
        if (it + 2 < NIT) { issue_stage(it + 2, (it + 2) % STAGES); cp_commit(); }

        const uint32_t aS = sbase + SMEM_A + s * A_ST_H * 2;
        const uint32_t bS = sbase + SMEM_B + s * B_ST_H * 2;
        #pragma unroll
        for (int ks = 0; ks < 2; ks++) {
            uint32_t afr[4][4];
            const int arL  = wm * 64 + (lane & 15);
            const int acol = ks * 16 + ((lane >> 4) << 3);
            #pragma unroll
            for (int mf = 0; mf < 4; mf++)
                ldmatrix_x4(afr[mf], aS + ((arL + mf * 16) * A_ROW_H + acol) * 2);

            uint32_t bfr[4][2];
            const int brL = ks * 16 + (lane & 15);
            #pragma unroll
            for (int nf = 0; nf < 4; nf++)
                ldmatrix_x2_trans(bfr[nf], bS + (brL * B_ROW_H + wn * 32 + nf * 8) * 2);

            #pragma unroll
            for (int mf = 0; mf < 4; mf++)
                #pragma unroll
                for (int nf = 0; nf < 4; nf++)
                    mma16816(acc[mf][nf], afr[mf], bfr[nf]);
        }
    }

    // epilogue: per-sample noisy bias fused, f32 stores
    const int gid = lane >> 2;
    const int tg  = lane & 3;
    #pragma unroll
    for (int nf = 0; nf < 4; nf++) {
        const int cc = n0 + wn * 32 + nf * 8 + tg * 2;
        const float mb0 = bias[cc]     * Berr[b * COUTC + cc];
        const float mb1 = bias[cc + 1] * Berr[b * COUTC + cc + 1];
        #pragma unroll
        for (int mf = 0; mf < 4; mf++) {
            const int r0 = m0 + wm * 64 + mf * 16 + gid;
            if (r0 < MM) {
                float2 v = make_float2(acc[mf][nf][0] + mb0, acc[mf][nf][1] + mb1);
                *reinterpret_cast<float2*>(&out[((size_t)b * MM + r0) * NNTOT + cc]) = v;
            }
            const int r1 = r0 + 8;
            if (r1 < MM) {
                float2 v = make_float2(acc[mf][nf][2] + mb0, acc[mf][nf][3] + mb1);
                *reinterpret_cast<float2*>(&out[((size_t)b * MM + r1) * NNTOT + cc]) = v;
            }
        }
    }
}

// ---------------- launch ----------------
extern "C" void kernel_launch(void* const* d_in, const int* in_sizes, int n_in,
                              void* d_out, int out_size) {
    (void)in_sizes; (void)n_in; (void)out_size;
    const float* X    = (const float*)d_in[0];
    const float* W    = (const float*)d_in[1];
    const float* bias = (const float*)d_in[2];
    const float* Werr = (const float*)d_in[3];
    const float* Berr = (const float*)d_in[4];
    float* out = (float*)d_out;

    prep_kernel<<<XBLOCKS + WBLOCKS, 256>>>(X, W, Werr);

    static bool attr_set = false;
    if (!attr_set) {
        cudaFuncSetAttribute(conv_gemm_kernel,
                             cudaFuncAttributeMaxDynamicSharedMemorySize, SMEM_TOTAL);
        attr_set = true;
    }
    dim3 grid(NNTOT / BN, (MM + BM - 1) / BM, BB);   // (2, 31, 64)
    conv_gemm_kernel<<<grid, NTHREADS, SMEM_TOTAL>>>(bias, Berr, out);
}

// round 5
// speedup vs baseline: 1.2343x; 1.0503x over previous
#include <cuda_runtime.h>
#include <cuda_fp16.h>
#include <cstdint>

// ---------------- problem constants ----------------
#define BB    64
#define HH    64
#define WWID  64
#define CINC  128
#define COUTC 256
#define HOUT  62
#define WOUT  62
#define MM    3844
#define KKTOT 1152
#define NNTOT 256

// ---------------- GEMM tiling ----------------
#define BM     128
#define BN     128
#define BK     64
#define NIT    (KKTOT / BK)   // 18
#define NTHREADS 256

// smem (halves): As[s][128][72], Bs[s][64][136]
#define A_ROW_H 72
#define B_ROW_H 136
#define A_ST_H  (BM * A_ROW_H)   // 9216 halves  = 18432 B
#define B_ST_H  (BK * B_ROW_H)   // 8704 halves  = 17408 B
#define SMEM_A  0
#define SMEM_B  (2 * A_ST_H * 2)                 // 36864
#define SMEM_TOTAL (SMEM_B + 2 * B_ST_H * 2)     // 71680

// ---------------- scratch ----------------
__device__ __half g_Xh[(size_t)BB * HH * WWID * CINC];   // X fp16 NHWC
__device__ __half g_Wh[(size_t)BB * KKTOT * COUTC];      // memW fp16 [b][k][n]

// ---------------- fused prep ----------------
#define XBLOCKS 32768
#define WBLOCKS 18432
__global__ void prep_kernel(const float* __restrict__ X,
                            const float* __restrict__ W,
                            const float* __restrict__ Werr) {
    if (blockIdx.x < XBLOCKS) {
        size_t i = ((size_t)blockIdx.x * blockDim.x + threadIdx.x) * 4;
        float4 v = *reinterpret_cast<const float4*>(X + i);
        __half2 h0 = __floats2half2_rn(v.x, v.y);
        __half2 h1 = __floats2half2_rn(v.z, v.w);
        uint2 o;
        o.x = *reinterpret_cast<uint32_t*>(&h0);
        o.y = *reinterpret_cast<uint32_t*>(&h1);
        *reinterpret_cast<uint2*>(g_Xh + i) = o;
    } else {
        size_t i = ((size_t)(blockIdx.x - XBLOCKS) * blockDim.x + threadIdx.x) * 4;
        size_t wi = i % ((size_t)KKTOT * COUTC);
        float4 w = *reinterpret_cast<const float4*>(W + wi);
        float4 e = *reinterpret_cast<const float4*>(Werr + i);
        __half2 h0 = __floats2half2_rn(w.x * e.x, w.y * e.y);
        __half2 h1 = __floats2half2_rn(w.z * e.z, w.w * e.w);
        uint2 o;
        o.x = *reinterpret_cast<uint32_t*>(&h0);
        o.y = *reinterpret_cast<uint32_t*>(&h1);
        *reinterpret_cast<uint2*>(g_Wh + i) = o;
    }
}

// ---------------- PTX helpers ----------------
__device__ __forceinline__ void cp16(uint32_t dst, const void* src) {
    asm volatile("cp.async.cg.shared.global [%0], [%1], 16;\n" :: "r"(dst), "l"(src));
}
__device__ __forceinline__ void cp_commit() {
    asm volatile("cp.async.commit_group;\n" ::: "memory");
}
template <int N>
__device__ __forceinline__ void cp_wait() {
    asm volatile("cp.async.wait_group %0;\n" :: "n"(N) : "memory");
}
__device__ __forceinline__ void ldmatrix_x4(uint32_t* r, uint32_t addr) {
    asm volatile("ldmatrix.sync.aligned.m8n8.x4.shared.b16 {%0,%1,%2,%3}, [%4];\n"
                 : "=r"(r[0]), "=r"(r[1]), "=r"(r[2]), "=r"(r[3]) : "r"(addr));
}
__device__ __forceinline__ void ldmatrix_x2_trans(uint32_t* r, uint32_t addr) {
    asm volatile("ldmatrix.sync.aligned.m8n8.x2.trans.shared.b16 {%0,%1}, [%2];\n"
                 : "=r"(r[0]), "=r"(r[1]) : "r"(addr));
}
__device__ __forceinline__ void mma16816(float* c, const uint32_t* a, const uint32_t* b) {
    asm volatile(
        "mma.sync.aligned.m16n8k16.row.col.f32.f16.f16.f32 "
        "{%0,%1,%2,%3}, {%4,%5,%6,%7}, {%8,%9}, {%0,%1,%2,%3};\n"
        : "+f"(c[0]), "+f"(c[1]), "+f"(c[2]), "+f"(c[3])
        : "r"(a[0]), "r"(a[1]), "r"(a[2]), "r"(a[3]), "r"(b[0]), "r"(b[1]));
}

// ---------------- main GEMM ----------------
// grid (2, 31, 64), 256 threads (2x4 warps, warp tile 64x32), BK=64 double-buffered
__global__ __launch_bounds__(NTHREADS, 2)
void conv_gemm_kernel(const float* __restrict__ bias,
                      const float* __restrict__ Berr,
                      float* __restrict__ out) {
    extern __shared__ __align__(16) char smem[];
    const uint32_t sbase = (uint32_t)__cvta_generic_to_shared(smem);

    const int tid  = threadIdx.x;
    const int warp = tid >> 5;
    const int lane = tid & 31;
    const int wm = warp >> 2;
    const int wn = warp & 3;
    const int n0 = blockIdx.x * BN;
    const int m0 = blockIdx.y * BM;
    const int b  = blockIdx.z;

    float acc[4][4][4];
    #pragma unroll
    for (int mf = 0; mf < 4; mf++)
        #pragma unroll
        for (int nf = 0; nf < 4; nf++)
            #pragma unroll
            for (int r = 0; r < 4; r++) acc[mf][nf][r] = 0.f;

    // A: 128 rows x 8 chunks = 1024 chunks/stage -> 4/thread
    const int arow0 = tid >> 3;       // +32 per j
    const int aseg  = tid & 7;
    size_t abase[4];
    #pragma unroll
    for (int j = 0; j < 4; j++) {
        int m = m0 + arow0 + j * 32;
        if (m >= MM) m = 0;
        int ho = m / WOUT;
        int wo = m - ho * WOUT;
        abase[j] = (((size_t)b * HH + ho) * WWID + wo) * CINC;
    }
    const size_t wbase = (size_t)b * KKTOT * COUTC;

    auto issue_stage = [&](int it, int slot) {
        const int k0 = it * BK;
        const int tap = k0 >> 7;               // BK=64: 2 its per tap
        const int c0  = k0 & 127;
        const int kh  = tap / 3;
        const int kw  = tap - kh * 3;
        const size_t tapoff = ((size_t)kh * WWID + kw) * CINC + c0;
        const uint32_t a0 = sbase + SMEM_A + slot * A_ST_H * 2;
        const uint32_t b0 = sbase + SMEM_B + slot * B_ST_H * 2;
        #pragma unroll
        for (int j = 0; j < 4; j++) {
            const __half* src = g_Xh + abase[j] + tapoff + aseg * 8;
            cp16(a0 + ((arow0 + j * 32) * A_ROW_H + aseg * 8) * 2, src);
        }
        #pragma unroll
        for (int j = 0; j < 4; j++) {          // B: 64 rows x 16 chunks
            int c = tid + j * 256;
            int row = c >> 4;
            int seg = c & 15;
            const __half* src = g_Wh + wbase + (size_t)(k0 + row) * COUTC + n0 + seg * 8;
            cp16(b0 + (row * B_ROW_H + seg * 8) * 2, src);
        }
    };

    issue_stage(0, 0); cp_commit();

    for (int it = 0; it < NIT; it++) {
        const int s = it & 1;
        cp_wait<0>();
        __syncthreads();
        if (it + 1 < NIT) { issue_stage(it + 1, s ^ 1); cp_commit(); }

        const uint32_t aS = sbase + SMEM_A + s * A_ST_H * 2;
        const uint32_t bS = sbase + SMEM_B + s * B_ST_H * 2;
        #pragma unroll
        for (int ks = 0; ks < 4; ks++) {
            uint32_t afr[4][4];
            const int arL  = wm * 64 + (lane & 15);
            const int acol = ks * 16 + ((lane >> 4) << 3);
            #pragma unroll
            for (int mf = 0; mf < 4; mf++)
                ldmatrix_x4(afr[mf], aS + ((arL + mf * 16) * A_ROW_H + acol) * 2);

            uint32_t bfr[4][2];
            const int brL = ks * 16 + (lane & 15);
            #pragma unroll
            for (int nf = 0; nf < 4; nf++)
                ldmatrix_x2_trans(bfr[nf], bS + (brL * B_ROW_H + wn * 32 + nf * 8) * 2);

            #pragma unroll
            for (int mf = 0; mf < 4; mf++)
                #pragma unroll
                for (int nf = 0; nf < 4; nf++)
                    mma16816(acc[mf][nf], afr[mf], bfr[nf]);
        }
        __syncthreads();   // all warps done reading stage s before it+2 overwrites
    }

    // epilogue: fused noisy bias, f32 stores
    const int gid = lane >> 2;
    const int tg  = lane & 3;
    #pragma unroll
    for (int nf = 0; nf < 4; nf++) {
        const int cc = n0 + wn * 32 + nf * 8 + tg * 2;
        const float mb0 = bias[cc]     * Berr[b * COUTC + cc];
        const float mb1 = bias[cc + 1] * Berr[b * COUTC + cc + 1];
        #pragma unroll
        for (int mf = 0; mf < 4; mf++) {
            const int r0 = m0 + wm * 64 + mf * 16 + gid;
            if (r0 < MM) {
                float2 v = make_float2(acc[mf][nf][0] + mb0, acc[mf][nf][1] + mb1);
                *reinterpret_cast<float2*>(&out[((size_t)b * MM + r0) * NNTOT + cc]) = v;
            }
            const int r1 = r0 + 8;
            if (r1 < MM) {
                float2 v = make_float2(acc[mf][nf][2] + mb0, acc[mf][nf][3] + mb1);
                *reinterpret_cast<float2*>(&out[((size_t)b * MM + r1) * NNTOT + cc]) = v;
            }
        }
    }
}

// ---------------- launch ----------------
extern "C" void kernel_launch(void* const* d_in, const int* in_sizes, int n_in,
                              void* d_out, int out_size) {
    (void)in_sizes; (void)n_in; (void)out_size;
    const float* X    = (const float*)d_in[0];
    const float* W    = (const float*)d_in[1];
    const float* bias = (const float*)d_in[2];
    const float* Werr = (const float*)d_in[3];
    const float* Berr = (const float*)d_in[4];
    float* out = (float*)d_out;

    prep_kernel<<<XBLOCKS + WBLOCKS, 256>>>(X, W, Werr);

    static bool attr_set = false;
    if (!attr_set) {
        cudaFuncSetAttribute(conv_gemm_kernel,
                             cudaFuncAttributeMaxDynamicSharedMemorySize, SMEM_TOTAL);
        attr_set = true;
    }
    dim3 grid(NNTOT / BN, (MM + BM - 1) / BM, BB);   // (2, 31, 64)
    conv_gemm_kernel<<<grid, NTHREADS, SMEM_TOTAL>>>(bias, Berr, out);
}